// round 7
// baseline (speedup 1.0000x reference)
#include <cuda_runtime.h>
#include <math.h>

// Problem dims (fixed by the dataset)
#define BB 4
#define NN 65536
#define CC 256
#define LL 64
#define SS 64
#define AA 16
#define BN (BB*NN)   // 262144 tokens

// ---------------- scratch (static device globals: no allocations allowed) ---
__device__ float g_w[(size_t)BN*SS];        // softmax assignment weights (B,N,S)
__device__ float g_shared[(size_t)BN*LL];   // 'shared' lowrank; later reused as 'act'
__device__ float g_y[(size_t)BN*CC];        // x after slice-reader residual
__device__ float g_sacc[BB*SS*CC];          // slice accumulator
__device__ float g_wsum[BB*SS];             // w column sums
__device__ float g_st[BB*SS*CC];            // slice tokens after LatentTransition

// ---------------- helpers ---------------------------------------------------
__device__ __forceinline__ float warp_sum(float v){
#pragma unroll
    for (int o = 16; o > 0; o >>= 1) v += __shfl_xor_sync(0xffffffffu, v, o);
    return v;
}
__device__ __forceinline__ float warp_max(float v){
#pragma unroll
    for (int o = 16; o > 0; o >>= 1) v = fmaxf(v, __shfl_xor_sync(0xffffffffu, v, o));
    return v;
}
__device__ __forceinline__ float gelu_exact(float x){
    return 0.5f * x * (1.0f + erff(x * 0.7071067811865476f));
}
__device__ __forceinline__ float sigmoid_(float x){
    return 1.0f / (1.0f + expf(-x));
}

// ---------------- zero the accumulators (graph-replay safe) -----------------
__global__ void hf_zero(){
    int i = blockIdx.x * 256 + threadIdx.x;
    if (i < BB*SS*CC) g_sacc[i] = 0.0f;
    if (i < BB*SS)    g_wsum[i] = 0.0f;
}

// ---------------- A1: LN1 + shared + assignment softmax ---------------------
// 256 threads, warp = 1 token, 8 tokens/warp-loop -> 64 tokens per block.
__global__ void hf_a1(const float* __restrict__ x, const float* __restrict__ geom,
                      const float* __restrict__ ln1g, const float* __restrict__ ln1b,
                      const float* __restrict__ W1, const float* __restrict__ b1,
                      const float* __restrict__ W3, const float* __restrict__ b3)
{
    extern __shared__ float sm[];
    float* sW1 = sm;                 // 256*64
    float* sW3 = sW1 + CC*LL;        // 128*64
    float* sb1 = sW3 + 2*LL*SS;      // 64
    float* sb3 = sb1 + LL;           // 64
    float* sg  = sb3 + SS;           // 256
    float* sb  = sg  + CC;           // 256
    float* shh = sb  + CC;           // 8*256 per-warp h
    float* ssh = shh + 8*CC;         // 8*64 per-warp shared
    float* sge = ssh + 8*LL;         // 8*64 per-warp geometry

    int tid = threadIdx.x;
    for (int i = tid; i < CC*LL;   i += 256) sW1[i] = W1[i];
    for (int i = tid; i < 2*LL*SS; i += 256) sW3[i] = W3[i];
    if (tid < LL) sb1[tid] = b1[tid];
    if (tid < SS) sb3[tid] = b3[tid];
    if (tid < CC) { sg[tid] = ln1g[tid]; sb[tid] = ln1b[tid]; }
    __syncthreads();

    int warp = tid >> 5, lane = tid & 31;
    float* hb  = shh + warp*CC;
    float* shb = ssh + warp*LL;
    float* geb = sge + warp*LL;
    const float2* w1v = (const float2*)sW1;
    const float2* w3v = (const float2*)sW3;

    for (int it = 0; it < 8; it++){
        int t = blockIdx.x*64 + warp*8 + it;
        __syncwarp();  // previous iteration's smem reads complete

        const float* xp = x + (size_t)t*CC;
        float xv[8];
#pragma unroll
        for (int j = 0; j < 8; j++) xv[j] = xp[lane + 32*j];
        float s1 = 0.f, s2 = 0.f;
#pragma unroll
        for (int j = 0; j < 8; j++){ s1 += xv[j]; s2 += xv[j]*xv[j]; }
        s1 = warp_sum(s1); s2 = warp_sum(s2);
        float mean = s1 * (1.0f/CC);
        float var  = s2 * (1.0f/CC) - mean*mean;
        float rstd = rsqrtf(var + 1e-5f);
#pragma unroll
        for (int j = 0; j < 8; j++){
            int c = lane + 32*j;
            hb[c] = (xv[j]-mean)*rstd*sg[c] + sb[c];
        }
        __syncwarp();

        // shared[l] for l = 2*lane, 2*lane+1
        float a0 = sb1[2*lane], a1 = sb1[2*lane+1];
#pragma unroll 4
        for (int c = 0; c < CC; c++){
            float hv = hb[c];
            float2 wv = w1v[c*32 + lane];
            a0 = fmaf(hv, wv.x, a0);
            a1 = fmaf(hv, wv.y, a1);
        }
        shb[2*lane] = a0; shb[2*lane+1] = a1;
        ((float2*)(g_shared + (size_t)t*LL))[lane] = make_float2(a0, a1);

        float2 gv = ((const float2*)(geom + (size_t)t*LL))[lane];
        geb[2*lane] = gv.x; geb[2*lane+1] = gv.y;
        __syncwarp();

        // logits over concat(shared, geom) for s = 2*lane, 2*lane+1
        float l0 = sb3[2*lane], l1 = sb3[2*lane+1];
#pragma unroll 4
        for (int k = 0; k < LL; k++){
            float v = shb[k];
            float2 wv = w3v[k*32 + lane];
            l0 = fmaf(v, wv.x, l0);
            l1 = fmaf(v, wv.y, l1);
        }
#pragma unroll 4
        for (int k = 0; k < LL; k++){
            float v = geb[k];
            float2 wv = w3v[(LL+k)*32 + lane];
            l0 = fmaf(v, wv.x, l0);
            l1 = fmaf(v, wv.y, l1);
        }
        float m  = warp_max(fmaxf(l0, l1));
        float e0 = expf(l0 - m), e1 = expf(l1 - m);
        float inv = 1.0f / warp_sum(e0 + e1);
        ((float2*)(g_w + (size_t)t*SS))[lane] = make_float2(e0*inv, e1*inv);
    }
}

// ---------------- A2: feat + slice accumulation GEMM -------------------------
// 256 threads, 8 tiles of 64 tokens = 512 tokens/block.
__global__ void hf_a2(const float* __restrict__ W2, const float* __restrict__ b2)
{
    extern __shared__ float sm[];
    float* sW2 = sm;                // 64*256
    float* sb2 = sW2 + LL*CC;       // 256
    float* sft = sb2 + CC;          // 64*256 feat tile
    float* swt = sft + 64*CC;       // 64*64  w tile
    float* ssb = swt + 64*SS;       // 8*64 per-warp shared buf

    int tid = threadIdx.x, warp = tid >> 5, lane = tid & 31;
    for (int i = tid; i < LL*CC; i += 256) sW2[i] = W2[i];
    if (tid < CC) sb2[tid] = b2[tid];

    float acc[8][8];
#pragma unroll
    for (int i = 0; i < 8; i++)
#pragma unroll
        for (int j = 0; j < 8; j++) acc[i][j] = 0.0f;
    float wsr = 0.0f;
    int s0 = warp * 8;
    float* shb = ssb + warp*LL;

    for (int tile = 0; tile < 8; tile++){
        __syncthreads();   // previous GEMM reads done; sW2/sb2 visible on tile 0
        int base = blockIdx.x*512 + tile*64;
        for (int i = tid; i < 64*SS; i += 256) swt[i] = g_w[(size_t)base*SS + i];

        // compute feat for 8 tokens per warp into the feat tile
        for (int it = 0; it < 8; it++){
            int tl  = warp*8 + it;
            int tok = base + tl;
            float2 shv = ((const float2*)(g_shared + (size_t)tok*LL))[lane];
            shb[2*lane] = shv.x; shb[2*lane+1] = shv.y;
            __syncwarp();
            float f[8];
#pragma unroll
            for (int j = 0; j < 8; j++) f[j] = sb2[lane + 32*j];
#pragma unroll 2
            for (int l = 0; l < LL; l++){
                float sv = shb[l];
#pragma unroll
                for (int j = 0; j < 8; j++)
                    f[j] = fmaf(sv, sW2[l*CC + lane + 32*j], f[j]);
            }
#pragma unroll
            for (int j = 0; j < 8; j++) sft[tl*CC + lane + 32*j] = f[j];
            __syncwarp();  // shb reads done before next overwrite
        }
        __syncthreads();

        // cooperative outer-product: acc[s0+i][lane+32j] += w[t][s0+i]*feat[t][...]
        for (int t = 0; t < 64; t++){
            float wv[8], fv[8];
#pragma unroll
            for (int i = 0; i < 8; i++) wv[i] = swt[t*SS + s0 + i];
#pragma unroll
            for (int j = 0; j < 8; j++) fv[j] = sft[t*CC + lane + 32*j];
#pragma unroll
            for (int i = 0; i < 8; i++)
#pragma unroll
                for (int j = 0; j < 8; j++)
                    acc[i][j] = fmaf(wv[i], fv[j], acc[i][j]);
        }
        if (tid < SS){
            for (int t = 0; t < 64; t++) wsr += swt[t*SS + tid];
        }
    }

    int b = blockIdx.x >> 7;   // 128 blocks per batch
    float* dst = g_sacc + b*SS*CC;
#pragma unroll
    for (int i = 0; i < 8; i++)
#pragma unroll
        for (int j = 0; j < 8; j++)
            atomicAdd(&dst[(s0+i)*CC + lane + 32*j], acc[i][j]);
    if (tid < SS) atomicAdd(&g_wsum[b*SS + tid], wsr);
}

// ---------------- B: slice normalize + LatentTransition (tiny) --------------
__global__ void hf_b(const float* __restrict__ dW,  const float* __restrict__ db,
                     const float* __restrict__ dng, const float* __restrict__ dnb,
                     const float* __restrict__ aW,  const float* __restrict__ ab,
                     const float* __restrict__ selfW, const float* __restrict__ ctxW,
                     const float* __restrict__ ong, const float* __restrict__ onb,
                     const float* __restrict__ uW,  const float* __restrict__ ub)
{
    extern __shared__ float sm[];
    float* sl     = sm;                  // 64*256 slice tokens
    float* wsinv  = sl + SS*CC;          // 64
    float* dsm    = wsinv + SS;          // 64*64
    float* lsm    = dsm + SS*LL;         // 64*64
    float* awm    = lsm + SS*LL;         // 64*16
    float* awsinv = awm + SS*AA;         // 16
    float* anch   = awsinv + AA;         // 16*64
    float* ctxm   = anch + AA*LL;        // 64*64
    float* ulm    = ctxm + SS*LL;        // 64*64

    int tid = threadIdx.x, b = blockIdx.x;
    for (int i = tid; i < SS*CC; i += 256) sl[i] = g_sacc[b*SS*CC + i];
    if (tid < SS) wsinv[tid] = 1.0f / fmaxf(g_wsum[b*SS + tid], 1e-6f);
    __syncthreads();
    for (int i = tid; i < SS*CC; i += 256) sl[i] *= wsinv[i >> 8];
    __syncthreads();

    // ds = slice @ lt_down_W + b
    for (int i = tid; i < SS*LL; i += 256){
        int s = i >> 6, l = i & 63;
        float accv = db[l];
        const float* row = sl + s*CC;
        for (int c = 0; c < CC; c++) accv = fmaf(row[c], dW[c*LL + l], accv);
        dsm[i] = accv;
    }
    __syncthreads();

    // ls = LN(ds)
    if (tid < SS){
        int s = tid;
        float m = 0.f;
        for (int l = 0; l < LL; l++) m += dsm[s*LL + l];
        m *= (1.0f/LL);
        float v = 0.f;
        for (int l = 0; l < LL; l++){ float d = dsm[s*LL + l] - m; v += d*d; }
        v *= (1.0f/LL);
        float r = rsqrtf(v + 1e-5f);
        for (int l = 0; l < LL; l++)
            lsm[s*LL + l] = (dsm[s*LL + l] - m)*r*dng[l] + dnb[l];
    }
    __syncthreads();

    // aw = softmax(ls @ lt_anc_W + b)
    if (tid < SS){
        int s = tid;
        float lg[AA];
        for (int a = 0; a < AA; a++) lg[a] = ab[a];
        for (int l = 0; l < LL; l++){
            float v = lsm[s*LL + l];
            for (int a = 0; a < AA; a++) lg[a] = fmaf(v, aW[l*AA + a], lg[a]);
        }
        float m = lg[0];
        for (int a = 1; a < AA; a++) m = fmaxf(m, lg[a]);
        float ssum = 0.f;
        for (int a = 0; a < AA; a++){ lg[a] = expf(lg[a] - m); ssum += lg[a]; }
        float inv = 1.0f / ssum;
        for (int a = 0; a < AA; a++) awm[s*AA + a] = lg[a]*inv;
    }
    __syncthreads();

    if (tid < AA){
        float ssum = 0.f;
        for (int s = 0; s < SS; s++) ssum += awm[s*AA + tid];
        awsinv[tid] = 1.0f / fmaxf(ssum, 1e-6f);
    }
    __syncthreads();

    // anchor = (aw^T @ ls) / awsum
    for (int i = tid; i < AA*LL; i += 256){
        int a = i >> 6, d = i & 63;
        float accv = 0.f;
        for (int s = 0; s < SS; s++) accv = fmaf(awm[s*AA + a], lsm[s*LL + d], accv);
        anch[i] = accv * awsinv[a];
    }
    __syncthreads();

    // ctx = aw @ anchor
    for (int i = tid; i < SS*LL; i += 256){
        int s = i >> 6, d = i & 63;
        float accv = 0.f;
        for (int a = 0; a < AA; a++) accv = fmaf(awm[s*AA + a], anch[a*LL + d], accv);
        ctxm[i] = accv;
    }
    __syncthreads();

    // ul = ls + gelu(ls@selfW + ctx@ctxW)
    for (int i = tid; i < SS*LL; i += 256){
        int s = i >> 6, l = i & 63;
        float accv = 0.f;
        for (int d = 0; d < LL; d++) accv = fmaf(lsm[s*LL + d], selfW[d*LL + l], accv);
        for (int d = 0; d < LL; d++) accv = fmaf(ctxm[s*LL + d], ctxW[d*LL + l], accv);
        ulm[i] = lsm[i] + gelu_exact(accv);
    }
    __syncthreads();

    // LN(ul) in place
    if (tid < SS){
        int s = tid;
        float m = 0.f;
        for (int l = 0; l < LL; l++) m += ulm[s*LL + l];
        m *= (1.0f/LL);
        float v = 0.f;
        for (int l = 0; l < LL; l++){ float d = ulm[s*LL + l] - m; v += d*d; }
        v *= (1.0f/LL);
        float r = rsqrtf(v + 1e-5f);
        for (int l = 0; l < LL; l++)
            ulm[s*LL + l] = (ulm[s*LL + l] - m)*r*ong[l] + onb[l];
    }
    __syncthreads();

    // st = uln @ lt_up_W + b
    for (int i = tid; i < SS*CC; i += 256){
        int s = i >> 8, c = i & 255;
        float accv = ub[c];
        for (int l = 0; l < LL; l++) accv = fmaf(ulm[s*LL + l], uW[l*CC + c], accv);
        g_st[b*SS*CC + i] = accv;
    }
}

// ---------------- C1: reader residual + LN2 + GLU input ---------------------
// 256 threads, warp = 1 token, 16 tokens/warp -> 128 tokens per block.
__global__ void hf_c1(const float* __restrict__ x,
                      const float* __restrict__ g2, const float* __restrict__ b2,
                      const float* __restrict__ Win, const float* __restrict__ bin)
{
    extern __shared__ float sm[];
    float* sst  = sm;                  // 64*256 st for this batch
    float* sWin = sst + SS*CC;         // 256*128
    float* sbin = sWin + CC*2*LL;      // 128
    float* sg2  = sbin + 2*LL;         // 256
    float* sb2  = sg2 + CC;            // 256
    float* shh  = sb2 + CC;            // 8*256 per-warp h
    float* swb  = shh + 8*CC;          // 8*64 per-warp w

    int tid = threadIdx.x, warp = tid >> 5, lane = tid & 31;
    int b = blockIdx.x >> 9;   // 512 blocks per batch
    for (int i = tid; i < SS*CC;   i += 256) sst[i]  = g_st[b*SS*CC + i];
    for (int i = tid; i < CC*2*LL; i += 256) sWin[i] = Win[i];
    if (tid < 2*LL) sbin[tid] = bin[tid];
    if (tid < CC) { sg2[tid] = g2[tid]; sb2[tid] = b2[tid]; }
    __syncthreads();

    float* hb = shh + warp*CC;
    float* wb = swb + warp*LL;

    for (int it = 0; it < 16; it++){
        int tok = blockIdx.x*128 + warp*16 + it;
        __syncwarp();   // previous iteration's hb/wb reads done

        float2 wv2 = ((const float2*)(g_w + (size_t)tok*SS))[lane];
        wb[2*lane] = wv2.x; wb[2*lane+1] = wv2.y;

        const float* xp = x + (size_t)tok*CC;
        float yv[8];
#pragma unroll
        for (int j = 0; j < 8; j++) yv[j] = xp[lane + 32*j];
        __syncwarp();

        // y = x + w @ st
        for (int s = 0; s < SS; s++){
            float wv = wb[s];
#pragma unroll
            for (int j = 0; j < 8; j++)
                yv[j] = fmaf(wv, sst[s*CC + lane + 32*j], yv[j]);
        }
        float* yp = g_y + (size_t)tok*CC;
#pragma unroll
        for (int j = 0; j < 8; j++) yp[lane + 32*j] = yv[j];

        // LN2
        float s1 = 0.f, s2 = 0.f;
#pragma unroll
        for (int j = 0; j < 8; j++){ s1 += yv[j]; s2 += yv[j]*yv[j]; }
        s1 = warp_sum(s1); s2 = warp_sum(s2);
        float mean = s1 * (1.0f/CC);
        float var  = s2 * (1.0f/CC) - mean*mean;
        float rstd = rsqrtf(var + 1e-5f);
#pragma unroll
        for (int j = 0; j < 8; j++){
            int c = lane + 32*j;
            hb[c] = (yv[j]-mean)*rstd*sg2[c] + sb2[c];
        }
        __syncwarp();

        // vg = h @ cm_in_W + b ; lane owns k = lane, lane+32 (v), lane+64, lane+96 (g)
        float a0 = sbin[lane], a1 = sbin[lane+32], a2 = sbin[lane+64], a3 = sbin[lane+96];
#pragma unroll 2
        for (int c = 0; c < CC; c++){
            float hv = hb[c];
            const float* wr = sWin + c*(2*LL);
            a0 = fmaf(hv, wr[lane],      a0);
            a1 = fmaf(hv, wr[lane+32],   a1);
            a2 = fmaf(hv, wr[lane+64],   a2);
            a3 = fmaf(hv, wr[lane+96],   a3);
        }
        float act0 = gelu_exact(a0) * sigmoid_(a2);
        float act1 = gelu_exact(a1) * sigmoid_(a3);
        g_shared[(size_t)tok*LL + lane]      = act0;   // reuse buffer as 'act'
        g_shared[(size_t)tok*LL + lane + 32] = act1;
    }
}

// ---------------- C2: out = y + act @ cm_out_W + b --------------------------
__global__ void hf_c2(const float* __restrict__ Wout, const float* __restrict__ bout,
                      float* __restrict__ out)
{
    extern __shared__ float sm[];
    float* sW  = sm;              // 64*256
    float* sb  = sW + LL*CC;      // 256
    float* sab = sb + CC;         // 8*64

    int tid = threadIdx.x, warp = tid >> 5, lane = tid & 31;
    for (int i = tid; i < LL*CC; i += 256) sW[i] = Wout[i];
    if (tid < CC) sb[tid] = bout[tid];
    __syncthreads();

    float* ab = sab + warp*LL;
    for (int it = 0; it < 8; it++){
        int tok = blockIdx.x*64 + warp*8 + it;
        __syncwarp();
        float2 av = ((const float2*)(g_shared + (size_t)tok*LL))[lane];
        ab[2*lane] = av.x; ab[2*lane+1] = av.y;
        __syncwarp();
        float acc[8];
#pragma unroll
        for (int j = 0; j < 8; j++) acc[j] = sb[lane + 32*j];
#pragma unroll 2
        for (int l = 0; l < LL; l++){
            float a = ab[l];
#pragma unroll
            for (int j = 0; j < 8; j++)
                acc[j] = fmaf(a, sW[l*CC + lane + 32*j], acc[j]);
        }
        const float* yp = g_y + (size_t)tok*CC;
        float* op = out + (size_t)tok*CC;
#pragma unroll
        for (int j = 0; j < 8; j++){
            int c = lane + 32*j;
            op[c] = yp[c] + acc[j];
        }
    }
}

// ---------------- launcher ---------------------------------------------------
extern "C" void kernel_launch(void* const* d_in, const int* in_sizes, int n_in,
                              void* d_out, int out_size)
{
    const float* x    = (const float*)d_in[0];
    const float* geom = (const float*)d_in[1];
    const float* ln1g = (const float*)d_in[2];
    const float* ln1b = (const float*)d_in[3];
    const float* swW  = (const float*)d_in[4];
    const float* swb  = (const float*)d_in[5];
    const float* sfW  = (const float*)d_in[6];
    const float* sfb  = (const float*)d_in[7];
    const float* saW  = (const float*)d_in[8];
    const float* sab  = (const float*)d_in[9];
    const float* ldW  = (const float*)d_in[10];
    const float* ldb  = (const float*)d_in[11];
    const float* dng  = (const float*)d_in[12];
    const float* dnb  = (const float*)d_in[13];
    const float* laW  = (const float*)d_in[14];
    const float* lab  = (const float*)d_in[15];
    const float* lsW  = (const float*)d_in[16];
    const float* lcW  = (const float*)d_in[17];
    const float* ong  = (const float*)d_in[18];
    const float* onb  = (const float*)d_in[19];
    const float* luW  = (const float*)d_in[20];
    const float* lub  = (const float*)d_in[21];
    const float* ln2g = (const float*)d_in[22];
    const float* ln2b = (const float*)d_in[23];
    const float* ciW  = (const float*)d_in[24];
    const float* cib  = (const float*)d_in[25];
    const float* coW  = (const float*)d_in[26];
    const float* cob  = (const float*)d_in[27];
    float* out = (float*)d_out;

    const size_t smA1 = (size_t)(CC*LL + 2*LL*SS + LL + SS + CC + CC + 8*CC + 8*LL + 8*LL) * 4;
    const size_t smA2 = (size_t)(LL*CC + CC + 64*CC + 64*SS + 8*LL) * 4;
    const size_t smB  = (size_t)(SS*CC + SS + SS*LL + SS*LL + SS*AA + AA + AA*LL + SS*LL + SS*LL) * 4;
    const size_t smC1 = (size_t)(SS*CC + CC*2*LL + 2*LL + CC + CC + 8*CC + 8*LL) * 4;
    const size_t smC2 = (size_t)(LL*CC + CC + 8*LL) * 4;

    cudaFuncSetAttribute(hf_a1, cudaFuncAttributeMaxDynamicSharedMemorySize, (int)smA1);
    cudaFuncSetAttribute(hf_a2, cudaFuncAttributeMaxDynamicSharedMemorySize, (int)smA2);
    cudaFuncSetAttribute(hf_b,  cudaFuncAttributeMaxDynamicSharedMemorySize, (int)smB);
    cudaFuncSetAttribute(hf_c1, cudaFuncAttributeMaxDynamicSharedMemorySize, (int)smC1);
    cudaFuncSetAttribute(hf_c2, cudaFuncAttributeMaxDynamicSharedMemorySize, (int)smC2);

    hf_zero<<<(BB*SS*CC + 255)/256, 256>>>();
    hf_a1<<<BN/64,  256, smA1>>>(x, geom, ln1g, ln1b, swW, swb, saW, sab);
    hf_a2<<<BN/512, 256, smA2>>>(sfW, sfb);
    hf_b <<<BB,     256, smB >>>(ldW, ldb, dng, dnb, laW, lab, lsW, lcW, ong, onb, luW, lub);
    hf_c1<<<BN/128, 256, smC1>>>(x, ln2g, ln2b, ciW, cib);
    hf_c2<<<BN/64,  256, smC2>>>(coW, cob, out);
}

// round 10
// speedup vs baseline: 2.1305x; 2.1305x over previous
#include <cuda_runtime.h>
#include <math.h>

// Problem dims (fixed by the dataset)
#define BB 4
#define NN 65536
#define CC 256
#define LL 64
#define SS 64
#define AA 16
#define BN (BB*NN)   // 262144 tokens

// ---------------- scratch (static device globals: no allocations allowed) ---
__device__ float g_w[(size_t)BN*SS];        // softmax assignment weights (B,N,S)
__device__ float g_act[(size_t)BN*LL];      // GLU activations
__device__ float g_y[(size_t)BN*CC];        // x after slice-reader residual
__device__ float g_stats[(size_t)BN*2];     // LN2 mean/rstd per token
__device__ float g_tacc[BB*SS*LL];          // w^T @ shared accumulator
__device__ float g_wsum[BB*SS];             // w column sums
__device__ float g_st[BB*SS*CC];            // slice tokens after LatentTransition

// ---------------- helpers ---------------------------------------------------
__device__ __forceinline__ float warp_sum(float v){
#pragma unroll
    for (int o = 16; o > 0; o >>= 1) v += __shfl_xor_sync(0xffffffffu, v, o);
    return v;
}
__device__ __forceinline__ float gelu_exact(float x){
    return 0.5f * x * (1.0f + erff(x * 0.7071067811865476f));
}
__device__ __forceinline__ float sigmoid_(float x){
    return 1.0f / (1.0f + expf(-x));
}

// ---------------- zero the accumulators (graph-replay safe) -----------------
__global__ void hf_zero(){
    int i = blockIdx.x * 256 + threadIdx.x;
    if (i < BB*SS*LL) g_tacc[i] = 0.0f;
    if (i < BB*SS)    g_wsum[i] = 0.0f;
}

// =====================================================================
// K2: per 256-token tile: LN1 -> shared = h@W1+b1 -> logits -> softmax w
//     -> write w, accumulate tacc += w^T @ shared, wsum += colsum(w)
// 256 threads. Register blocking 8x8 (32 token-groups x 8 out-groups).
// =====================================================================
__global__ void __launch_bounds__(256,1)
hf_k2(const float* __restrict__ x, const float* __restrict__ geom,
      const float* __restrict__ ln1g, const float* __restrict__ ln1b,
      const float* __restrict__ W1, const float* __restrict__ b1,
      const float* __restrict__ W3, const float* __restrict__ b3)
{
    extern __shared__ float sm[];
    float* sA     = sm;               // 256*65  (h-chunk / geom / logits+w)
    float* sB     = sA + 256*65;      // 256*64  (W1, later W3 in first 128*64)
    float* sC     = sB + 256*64;      // 256*65  (shared tile)
    float* sStats = sC + 256*65;      // 512

    int tid = threadIdx.x, wid = tid >> 5, lane = tid & 31;
    int base  = blockIdx.x * 256;
    int batch = base >> 16;

    // ---- LN1 stats (warp per token, 32 tokens per warp) ----
    for (int r = 0; r < 32; r++){
        int t = wid*32 + r;
        const float* xp = x + (size_t)(base + t)*CC;
        float s1 = 0.f, s2 = 0.f;
#pragma unroll
        for (int j = 0; j < 8; j++){ float v = xp[lane + 32*j]; s1 += v; s2 += v*v; }
        s1 = warp_sum(s1); s2 = warp_sum(s2);
        if (lane == 0){
            float m = s1 * (1.0f/CC);
            float var = s2 * (1.0f/CC) - m*m;
            sStats[2*t]   = m;
            sStats[2*t+1] = rsqrtf(var + 1e-5f);
        }
    }
    // W1 resident
    for (int i = tid; i < 256*64; i += 256) sB[i] = W1[i];

    int tg = tid >> 3, og = tid & 7;
    float acc[8][8];
#pragma unroll
    for (int i = 0; i < 8; i++)
#pragma unroll
        for (int j = 0; j < 8; j++) acc[i][j] = b1[og*8 + j];

    const float4* w4 = (const float4*)sB;

    // ---- GEMM1: shared = h @ W1, K=256 in 4 chunks ----
    for (int kc = 0; kc < 4; kc++){
        __syncthreads();
        for (int idx = tid; idx < 256*64; idx += 256){
            int t = idx >> 6, c = idx & 63;
            int kg = kc*64 + c;
            float v = x[(size_t)(base + t)*CC + kg];
            sA[t*65 + c] = (v - sStats[2*t]) * sStats[2*t+1] * ln1g[kg] + ln1b[kg];
        }
        __syncthreads();
        for (int k = 0; k < 64; k++){
            int kg = kc*64 + k;
            float hv[8];
#pragma unroll
            for (int i = 0; i < 8; i++) hv[i] = sA[(tg*8+i)*65 + k];
            float4 wa = w4[kg*16 + og*2];
            float4 wb = w4[kg*16 + og*2 + 1];
#pragma unroll
            for (int i = 0; i < 8; i++){
                float h = hv[i];
                acc[i][0] = fmaf(h, wa.x, acc[i][0]);
                acc[i][1] = fmaf(h, wa.y, acc[i][1]);
                acc[i][2] = fmaf(h, wa.z, acc[i][2]);
                acc[i][3] = fmaf(h, wa.w, acc[i][3]);
                acc[i][4] = fmaf(h, wb.x, acc[i][4]);
                acc[i][5] = fmaf(h, wb.y, acc[i][5]);
                acc[i][6] = fmaf(h, wb.z, acc[i][6]);
                acc[i][7] = fmaf(h, wb.w, acc[i][7]);
            }
        }
    }
    // write shared tile to sC
#pragma unroll
    for (int i = 0; i < 8; i++)
#pragma unroll
        for (int j = 0; j < 8; j++)
            sC[(tg*8+i)*65 + og*8 + j] = acc[i][j];
    __syncthreads();

    // ---- stage geom + W3 ----
    for (int idx = tid; idx < 256*64; idx += 256){
        int t = idx >> 6, c = idx & 63;
        sA[t*65 + c] = geom[(size_t)(base + t)*64 + c];
    }
    for (int i = tid; i < 128*64; i += 256) sB[i] = W3[i];
#pragma unroll
    for (int i = 0; i < 8; i++)
#pragma unroll
        for (int j = 0; j < 8; j++) acc[i][j] = b3[og*8 + j];
    __syncthreads();

    // ---- GEMM2: logits = shared@W3[:64] + geom@W3[64:] ----
    for (int k = 0; k < 64; k++){
        float hv[8];
#pragma unroll
        for (int i = 0; i < 8; i++) hv[i] = sC[(tg*8+i)*65 + k];
        float4 wa = w4[k*16 + og*2];
        float4 wb = w4[k*16 + og*2 + 1];
#pragma unroll
        for (int i = 0; i < 8; i++){
            float h = hv[i];
            acc[i][0] = fmaf(h, wa.x, acc[i][0]);
            acc[i][1] = fmaf(h, wa.y, acc[i][1]);
            acc[i][2] = fmaf(h, wa.z, acc[i][2]);
            acc[i][3] = fmaf(h, wa.w, acc[i][3]);
            acc[i][4] = fmaf(h, wb.x, acc[i][4]);
            acc[i][5] = fmaf(h, wb.y, acc[i][5]);
            acc[i][6] = fmaf(h, wb.z, acc[i][6]);
            acc[i][7] = fmaf(h, wb.w, acc[i][7]);
        }
    }
    for (int k = 0; k < 64; k++){
        float hv[8];
#pragma unroll
        for (int i = 0; i < 8; i++) hv[i] = sA[(tg*8+i)*65 + k];
        float4 wa = w4[(64+k)*16 + og*2];
        float4 wb = w4[(64+k)*16 + og*2 + 1];
#pragma unroll
        for (int i = 0; i < 8; i++){
            float h = hv[i];
            acc[i][0] = fmaf(h, wa.x, acc[i][0]);
            acc[i][1] = fmaf(h, wa.y, acc[i][1]);
            acc[i][2] = fmaf(h, wa.z, acc[i][2]);
            acc[i][3] = fmaf(h, wa.w, acc[i][3]);
            acc[i][4] = fmaf(h, wb.x, acc[i][4]);
            acc[i][5] = fmaf(h, wb.y, acc[i][5]);
            acc[i][6] = fmaf(h, wb.z, acc[i][6]);
            acc[i][7] = fmaf(h, wb.w, acc[i][7]);
        }
    }
    __syncthreads();   // geom reads done; overwrite sA with logits
#pragma unroll
    for (int i = 0; i < 8; i++)
#pragma unroll
        for (int j = 0; j < 8; j++)
            sA[(tg*8+i)*65 + og*8 + j] = acc[i][j];
    __syncthreads();

    // ---- softmax per token (thread = token) ----
    {
        float* row = sA + tid*65;
        float m = row[0];
#pragma unroll 8
        for (int c = 1; c < 64; c++) m = fmaxf(m, row[c]);
        float s = 0.f;
#pragma unroll 8
        for (int c = 0; c < 64; c++){ float e = expf(row[c] - m); row[c] = e; s += e; }
        float inv = 1.0f / s;
#pragma unroll 8
        for (int c = 0; c < 64; c++) row[c] *= inv;
    }
    __syncthreads();

    // ---- write w (coalesced), wsum ----
    for (int idx = tid; idx < 256*64; idx += 256){
        int t = idx >> 6, c = idx & 63;
        g_w[(size_t)(base + t)*64 + c] = sA[t*65 + c];
    }
    if (tid < 64){
        float s = 0.f;
        for (int t = 0; t < 256; t++) s += sA[t*65 + tid];
        atomicAdd(&g_wsum[batch*64 + tid], s);
    }

    // ---- tacc += w^T @ shared (64x64 output, 4x4 per thread) ----
    int sg = tid >> 4, cg = tid & 15;
    float ta[4][4];
#pragma unroll
    for (int ii = 0; ii < 4; ii++)
#pragma unroll
        for (int jj = 0; jj < 4; jj++) ta[ii][jj] = 0.0f;
    for (int t = 0; t < 256; t++){
        float wv[4], lv[4];
#pragma unroll
        for (int ii = 0; ii < 4; ii++) wv[ii] = sA[t*65 + sg*4 + ii];
#pragma unroll
        for (int jj = 0; jj < 4; jj++) lv[jj] = sC[t*65 + cg*4 + jj];
#pragma unroll
        for (int ii = 0; ii < 4; ii++)
#pragma unroll
            for (int jj = 0; jj < 4; jj++)
                ta[ii][jj] = fmaf(wv[ii], lv[jj], ta[ii][jj]);
    }
#pragma unroll
    for (int ii = 0; ii < 4; ii++)
#pragma unroll
        for (int jj = 0; jj < 4; jj++)
            atomicAdd(&g_tacc[batch*4096 + (sg*4+ii)*64 + cg*4 + jj], ta[ii][jj]);
}

// =====================================================================
// B: slice head (tacc@W2 -> slice) + LatentTransition (per batch)
// =====================================================================
__global__ void hf_b(const float* __restrict__ W2,  const float* __restrict__ b2,
                     const float* __restrict__ dW,  const float* __restrict__ db,
                     const float* __restrict__ dng, const float* __restrict__ dnb,
                     const float* __restrict__ aW,  const float* __restrict__ ab,
                     const float* __restrict__ selfW, const float* __restrict__ ctxW,
                     const float* __restrict__ ong, const float* __restrict__ onb,
                     const float* __restrict__ uW,  const float* __restrict__ ub)
{
    extern __shared__ float sm[];
    float* sl     = sm;                  // 64*256 slice tokens
    float* ta     = sl + SS*CC;          // 64*64  tacc
    float* ws     = ta + SS*LL;          // 64
    float* wsinv  = ws + SS;             // 64
    float* dsm    = wsinv + SS;          // 64*64
    float* lsm    = dsm + SS*LL;         // 64*64
    float* awm    = lsm + SS*LL;         // 64*16
    float* awsinv = awm + SS*AA;         // 16
    float* anch   = awsinv + AA;         // 16*64
    float* ctxm   = anch + AA*LL;        // 64*64
    float* ulm    = ctxm + SS*LL;        // 64*64

    int tid = threadIdx.x, b = blockIdx.x;
    for (int i = tid; i < SS*LL; i += 256) ta[i] = g_tacc[b*SS*LL + i];
    if (tid < SS){
        float wv = g_wsum[b*SS + tid];
        ws[tid] = wv;
        wsinv[tid] = 1.0f / fmaxf(wv, 1e-6f);
    }
    __syncthreads();

    // slice = (tacc @ W2 + wsum*b2) / clip(wsum)
    for (int i = tid; i < SS*CC; i += 256){
        int s = i >> 8, c = i & 255;
        float accv = 0.f;
        const float* tr = ta + s*LL;
        for (int l = 0; l < LL; l++) accv = fmaf(tr[l], W2[l*CC + c], accv);
        sl[i] = (accv + ws[s]*b2[c]) * wsinv[s];
    }
    __syncthreads();

    // ds = slice @ lt_down_W + b
    for (int i = tid; i < SS*LL; i += 256){
        int s = i >> 6, l = i & 63;
        float accv = db[l];
        const float* row = sl + s*CC;
        for (int c = 0; c < CC; c++) accv = fmaf(row[c], dW[c*LL + l], accv);
        dsm[i] = accv;
    }
    __syncthreads();

    // ls = LN(ds)
    if (tid < SS){
        int s = tid;
        float m = 0.f;
        for (int l = 0; l < LL; l++) m += dsm[s*LL + l];
        m *= (1.0f/LL);
        float v = 0.f;
        for (int l = 0; l < LL; l++){ float d = dsm[s*LL + l] - m; v += d*d; }
        v *= (1.0f/LL);
        float r = rsqrtf(v + 1e-5f);
        for (int l = 0; l < LL; l++)
            lsm[s*LL + l] = (dsm[s*LL + l] - m)*r*dng[l] + dnb[l];
    }
    __syncthreads();

    // aw = softmax(ls @ lt_anc_W + b)
    if (tid < SS){
        int s = tid;
        float lg[AA];
        for (int a = 0; a < AA; a++) lg[a] = ab[a];
        for (int l = 0; l < LL; l++){
            float v = lsm[s*LL + l];
            for (int a = 0; a < AA; a++) lg[a] = fmaf(v, aW[l*AA + a], lg[a]);
        }
        float m = lg[0];
        for (int a = 1; a < AA; a++) m = fmaxf(m, lg[a]);
        float ssum = 0.f;
        for (int a = 0; a < AA; a++){ lg[a] = expf(lg[a] - m); ssum += lg[a]; }
        float inv = 1.0f / ssum;
        for (int a = 0; a < AA; a++) awm[s*AA + a] = lg[a]*inv;
    }
    __syncthreads();

    if (tid < AA){
        float ssum = 0.f;
        for (int s = 0; s < SS; s++) ssum += awm[s*AA + tid];
        awsinv[tid] = 1.0f / fmaxf(ssum, 1e-6f);
    }
    __syncthreads();

    // anchor = (aw^T @ ls) / awsum
    for (int i = tid; i < AA*LL; i += 256){
        int a = i >> 6, d = i & 63;
        float accv = 0.f;
        for (int s = 0; s < SS; s++) accv = fmaf(awm[s*AA + a], lsm[s*LL + d], accv);
        anch[i] = accv * awsinv[a];
    }
    __syncthreads();

    // ctx = aw @ anchor
    for (int i = tid; i < SS*LL; i += 256){
        int s = i >> 6, d = i & 63;
        float accv = 0.f;
        for (int a = 0; a < AA; a++) accv = fmaf(awm[s*AA + a], anch[a*LL + d], accv);
        ctxm[i] = accv;
    }
    __syncthreads();

    // ul = ls + gelu(ls@selfW + ctx@ctxW)
    for (int i = tid; i < SS*LL; i += 256){
        int s = i >> 6, l = i & 63;
        float accv = 0.f;
        for (int d = 0; d < LL; d++) accv = fmaf(lsm[s*LL + d], selfW[d*LL + l], accv);
        for (int d = 0; d < LL; d++) accv = fmaf(ctxm[s*LL + d], ctxW[d*LL + l], accv);
        ulm[i] = lsm[i] + gelu_exact(accv);
    }
    __syncthreads();

    // LN(ul) in place
    if (tid < SS){
        int s = tid;
        float m = 0.f;
        for (int l = 0; l < LL; l++) m += ulm[s*LL + l];
        m *= (1.0f/LL);
        float v = 0.f;
        for (int l = 0; l < LL; l++){ float d = ulm[s*LL + l] - m; v += d*d; }
        v *= (1.0f/LL);
        float r = rsqrtf(v + 1e-5f);
        for (int l = 0; l < LL; l++)
            ulm[s*LL + l] = (ulm[s*LL + l] - m)*r*ong[l] + onb[l];
    }
    __syncthreads();

    // st = uln @ lt_up_W + b
    for (int i = tid; i < SS*CC; i += 256){
        int s = i >> 8, c = i & 255;
        float accv = ub[c];
        for (int l = 0; l < LL; l++) accv = fmaf(ulm[s*LL + l], uW[l*CC + c], accv);
        g_st[b*SS*CC + i] = accv;
    }
}

// =====================================================================
// K5: y = x + w @ st  (+ LN2 stats). 128 tokens x 256 cols, 512 threads.
// =====================================================================
__global__ void __launch_bounds__(512,1)
hf_k5(const float* __restrict__ x)
{
    extern __shared__ float sm[];
    float* sST = sm;            // 64*256
    float* sW  = sST + 64*256;  // 128*65
    int tid = threadIdx.x;
    int base  = blockIdx.x * 128;
    int batch = base >> 16;

    for (int i = tid; i < 64*256; i += 512) sST[i] = g_st[batch*16384 + i];
    for (int idx = tid; idx < 128*64; idx += 512){
        int t = idx >> 6, c = idx & 63;
        sW[t*65 + c] = g_w[(size_t)(base + t)*64 + c];
    }
    __syncthreads();

    int tg = tid >> 5, cg = tid & 31;
    float acc[8][8];
#pragma unroll
    for (int i = 0; i < 8; i++)
#pragma unroll
        for (int j = 0; j < 8; j++) acc[i][j] = 0.0f;

    const float4* st4 = (const float4*)sST;
    for (int k = 0; k < 64; k++){
        float wv[8];
#pragma unroll
        for (int i = 0; i < 8; i++) wv[i] = sW[(tg*8+i)*65 + k];
        float4 a = st4[k*64 + cg*2];
        float4 b = st4[k*64 + cg*2 + 1];
#pragma unroll
        for (int i = 0; i < 8; i++){
            float w = wv[i];
            acc[i][0] = fmaf(w, a.x, acc[i][0]);
            acc[i][1] = fmaf(w, a.y, acc[i][1]);
            acc[i][2] = fmaf(w, a.z, acc[i][2]);
            acc[i][3] = fmaf(w, a.w, acc[i][3]);
            acc[i][4] = fmaf(w, b.x, acc[i][4]);
            acc[i][5] = fmaf(w, b.y, acc[i][5]);
            acc[i][6] = fmaf(w, b.z, acc[i][6]);
            acc[i][7] = fmaf(w, b.w, acc[i][7]);
        }
    }
    __syncthreads();     // k-loop done; reuse sW for LN2 reduction

    float* sR = sW;      // [128][32] x 2 planes (8192 floats <= 8320)
#pragma unroll
    for (int i = 0; i < 8; i++){
        int tok = base + tg*8 + i;
        size_t ofs = (size_t)tok*256 + cg*8;
        float4 xa = *(const float4*)(x + ofs);
        float4 xb = *(const float4*)(x + ofs + 4);
        acc[i][0] += xa.x; acc[i][1] += xa.y; acc[i][2] += xa.z; acc[i][3] += xa.w;
        acc[i][4] += xb.x; acc[i][5] += xb.y; acc[i][6] += xb.z; acc[i][7] += xb.w;
        *(float4*)(g_y + ofs)     = make_float4(acc[i][0], acc[i][1], acc[i][2], acc[i][3]);
        *(float4*)(g_y + ofs + 4) = make_float4(acc[i][4], acc[i][5], acc[i][6], acc[i][7]);
        float s1 = 0.f, s2 = 0.f;
#pragma unroll
        for (int j = 0; j < 8; j++){ s1 += acc[i][j]; s2 += acc[i][j]*acc[i][j]; }
        sR[(tg*8+i)*32 + cg]        = s1;
        sR[4096 + (tg*8+i)*32 + cg] = s2;
    }
    __syncthreads();
    if (tid < 128){
        int t = tid;
        float S1 = 0.f, S2 = 0.f;
        for (int c = 0; c < 32; c++){ S1 += sR[t*32 + c]; S2 += sR[4096 + t*32 + c]; }
        float m = S1 * (1.0f/256.0f);
        float var = S2 * (1.0f/256.0f) - m*m;
        g_stats[(size_t)(base + t)*2]     = m;
        g_stats[(size_t)(base + t)*2 + 1] = rsqrtf(var + 1e-5f);
    }
}

// =====================================================================
// K6: vg = LN2(y) @ cm_in_W + b; act = gelu(v)*sigmoid(g)
// 128 tokens x 128 outs, 256 threads, 8x8 (thread cols: cg*4+j and 64+cg*4+j)
// =====================================================================
__global__ void __launch_bounds__(256,1)
hf_k6(const float* __restrict__ g2v, const float* __restrict__ b2v,
      const float* __restrict__ Win, const float* __restrict__ bin)
{
    extern __shared__ float sm[];
    float* sWin  = sm;            // 256*128
    float* sH    = sWin + 32768;  // 128*65
    float* sStat = sH + 8320;     // 256
    int tid = threadIdx.x;
    int base = blockIdx.x * 128;

    for (int i = tid; i < 32768; i += 256) sWin[i] = Win[i];
    if (tid < 128){
        sStat[2*tid]   = g_stats[(size_t)(base + tid)*2];
        sStat[2*tid+1] = g_stats[(size_t)(base + tid)*2 + 1];
    }

    int tg = tid >> 4, cg = tid & 15;
    float acc[8][8];
#pragma unroll
    for (int i = 0; i < 8; i++)
#pragma unroll
        for (int j = 0; j < 4; j++){
            acc[i][j]   = bin[cg*4 + j];
            acc[i][j+4] = bin[64 + cg*4 + j];
        }

    const float4* w4 = (const float4*)sWin;
    for (int kc = 0; kc < 4; kc++){
        __syncthreads();
        for (int idx = tid; idx < 128*64; idx += 256){
            int t = idx >> 6, c = idx & 63;
            int kg = kc*64 + c;
            float v = g_y[(size_t)(base + t)*256 + kg];
            sH[t*65 + c] = (v - sStat[2*t]) * sStat[2*t+1] * g2v[kg] + b2v[kg];
        }
        __syncthreads();
        for (int k = 0; k < 64; k++){
            int kg = kc*64 + k;
            float hv[8];
#pragma unroll
            for (int i = 0; i < 8; i++) hv[i] = sH[(tg*8+i)*65 + k];
            float4 a = w4[kg*32 + cg];        // v cols
            float4 b = w4[kg*32 + 16 + cg];   // g cols
#pragma unroll
            for (int i = 0; i < 8; i++){
                float h = hv[i];
                acc[i][0] = fmaf(h, a.x, acc[i][0]);
                acc[i][1] = fmaf(h, a.y, acc[i][1]);
                acc[i][2] = fmaf(h, a.z, acc[i][2]);
                acc[i][3] = fmaf(h, a.w, acc[i][3]);
                acc[i][4] = fmaf(h, b.x, acc[i][4]);
                acc[i][5] = fmaf(h, b.y, acc[i][5]);
                acc[i][6] = fmaf(h, b.z, acc[i][6]);
                acc[i][7] = fmaf(h, b.w, acc[i][7]);
            }
        }
    }
#pragma unroll
    for (int i = 0; i < 8; i++){
        int tok = base + tg*8 + i;
        float4 o;
        o.x = gelu_exact(acc[i][0]) * sigmoid_(acc[i][4]);
        o.y = gelu_exact(acc[i][1]) * sigmoid_(acc[i][5]);
        o.z = gelu_exact(acc[i][2]) * sigmoid_(acc[i][6]);
        o.w = gelu_exact(acc[i][3]) * sigmoid_(acc[i][7]);
        *(float4*)(g_act + (size_t)tok*64 + cg*4) = o;
    }
}

// =====================================================================
// K7: out = y + act @ cm_out_W + b. 128 tokens x 128-col half, 256 threads.
// =====================================================================
__global__ void __launch_bounds__(256,1)
hf_k7(const float* __restrict__ Wout, const float* __restrict__ bout,
      float* __restrict__ out)
{
    extern __shared__ float sm[];
    float* sA = sm;          // 128*65 act
    float* sW = sA + 8320;   // 64*128
    int tid = threadIdx.x;
    int bx = blockIdx.x;
    int half = bx & 1;
    int base = (bx >> 1) * 128;

    for (int idx = tid; idx < 128*64; idx += 256){
        int t = idx >> 6, c = idx & 63;
        sA[t*65 + c] = g_act[(size_t)(base + t)*64 + c];
    }
    for (int idx = tid; idx < 64*128; idx += 256){
        int l = idx >> 7, c = idx & 127;
        sW[idx] = Wout[l*256 + half*128 + c];
    }
    __syncthreads();

    int tg = tid >> 4, cg = tid & 15;
    float acc[8][8];
#pragma unroll
    for (int i = 0; i < 8; i++)
#pragma unroll
        for (int j = 0; j < 8; j++) acc[i][j] = bout[half*128 + cg*8 + j];

    const float4* w4 = (const float4*)sW;
    for (int k = 0; k < 64; k++){
        float av[8];
#pragma unroll
        for (int i = 0; i < 8; i++) av[i] = sA[(tg*8+i)*65 + k];
        float4 a = w4[k*32 + cg*2];
        float4 b = w4[k*32 + cg*2 + 1];
#pragma unroll
        for (int i = 0; i < 8; i++){
            float v = av[i];
            acc[i][0] = fmaf(v, a.x, acc[i][0]);
            acc[i][1] = fmaf(v, a.y, acc[i][1]);
            acc[i][2] = fmaf(v, a.z, acc[i][2]);
            acc[i][3] = fmaf(v, a.w, acc[i][3]);
            acc[i][4] = fmaf(v, b.x, acc[i][4]);
            acc[i][5] = fmaf(v, b.y, acc[i][5]);
            acc[i][6] = fmaf(v, b.z, acc[i][6]);
            acc[i][7] = fmaf(v, b.w, acc[i][7]);
        }
    }
#pragma unroll
    for (int i = 0; i < 8; i++){
        int tok = base + tg*8 + i;
        size_t ofs = (size_t)tok*256 + half*128 + cg*8;
        float4 ya = *(const float4*)(g_y + ofs);
        float4 yb = *(const float4*)(g_y + ofs + 4);
        *(float4*)(out + ofs)     = make_float4(ya.x + acc[i][0], ya.y + acc[i][1],
                                                ya.z + acc[i][2], ya.w + acc[i][3]);
        *(float4*)(out + ofs + 4) = make_float4(yb.x + acc[i][4], yb.y + acc[i][5],
                                                yb.z + acc[i][6], yb.w + acc[i][7]);
    }
}

// ---------------- launcher ---------------------------------------------------
extern "C" void kernel_launch(void* const* d_in, const int* in_sizes, int n_in,
                              void* d_out, int out_size)
{
    const float* x    = (const float*)d_in[0];
    const float* geom = (const float*)d_in[1];
    const float* ln1g = (const float*)d_in[2];
    const float* ln1b = (const float*)d_in[3];
    const float* swW  = (const float*)d_in[4];
    const float* swb  = (const float*)d_in[5];
    const float* sfW  = (const float*)d_in[6];
    const float* sfb  = (const float*)d_in[7];
    const float* saW  = (const float*)d_in[8];
    const float* sab  = (const float*)d_in[9];
    const float* ldW  = (const float*)d_in[10];
    const float* ldb  = (const float*)d_in[11];
    const float* dng  = (const float*)d_in[12];
    const float* dnb  = (const float*)d_in[13];
    const float* laW  = (const float*)d_in[14];
    const float* lab  = (const float*)d_in[15];
    const float* lsW  = (const float*)d_in[16];
    const float* lcW  = (const float*)d_in[17];
    const float* ong  = (const float*)d_in[18];
    const float* onb  = (const float*)d_in[19];
    const float* luW  = (const float*)d_in[20];
    const float* lub  = (const float*)d_in[21];
    const float* ln2g = (const float*)d_in[22];
    const float* ln2b = (const float*)d_in[23];
    const float* ciW  = (const float*)d_in[24];
    const float* cib  = (const float*)d_in[25];
    const float* coW  = (const float*)d_in[26];
    const float* cob  = (const float*)d_in[27];
    float* out = (float*)d_out;

    const size_t smK2 = (size_t)(256*65 + 256*64 + 256*65 + 512) * 4;           // ~200.7 KB
    const size_t smB  = (size_t)(SS*CC + SS*LL + SS + SS + SS*LL + SS*LL +
                                 SS*AA + AA + AA*LL + SS*LL + SS*LL) * 4;       // ~156 KB
    const size_t smK5 = (size_t)(64*256 + 128*65) * 4;                          // ~96.5 KB
    const size_t smK6 = (size_t)(32768 + 8320 + 256) * 4;                       // ~161.5 KB
    const size_t smK7 = (size_t)(8320 + 8192) * 4;                              // ~64.5 KB

    cudaFuncSetAttribute(hf_k2, cudaFuncAttributeMaxDynamicSharedMemorySize, (int)smK2);
    cudaFuncSetAttribute(hf_b,  cudaFuncAttributeMaxDynamicSharedMemorySize, (int)smB);
    cudaFuncSetAttribute(hf_k5, cudaFuncAttributeMaxDynamicSharedMemorySize, (int)smK5);
    cudaFuncSetAttribute(hf_k6, cudaFuncAttributeMaxDynamicSharedMemorySize, (int)smK6);
    cudaFuncSetAttribute(hf_k7, cudaFuncAttributeMaxDynamicSharedMemorySize, (int)smK7);

    hf_zero<<<(BB*SS*LL + 255)/256, 256>>>();
    hf_k2<<<BN/256, 256, smK2>>>(x, geom, ln1g, ln1b, swW, swb, saW, sab);
    hf_b <<<BB,     256, smB >>>(sfW, sfb, ldW, ldb, dng, dnb, laW, lab,
                                 lsW, lcW, ong, onb, luW, lub);
    hf_k5<<<BN/128, 512, smK5>>>(x);
    hf_k6<<<BN/128, 256, smK6>>>(ln2g, ln2b, ciW, cib);
    hf_k7<<<BN/64,  256, smK7>>>(coW, cob, out);
}

// round 11
// speedup vs baseline: 2.4712x; 1.1599x over previous
#include <cuda_runtime.h>
#include <math.h>

// Problem dims (fixed by the dataset)
#define BB 4
#define NN 65536
#define CC 256
#define LL 64
#define SS 64
#define AA 16
#define BN (BB*NN)   // 262144 tokens

// ---------------- scratch (static device globals: no allocations allowed) ---
__device__ float g_w[(size_t)BN*SS];        // softmax assignment weights (B,N,S)
__device__ float g_act[(size_t)BN*LL];      // GLU activations
__device__ float g_y[(size_t)BN*CC];        // x after slice-reader residual
__device__ float g_stats[(size_t)BN*2];     // LN2 mean/rstd per token
__device__ float g_tacc[BB*SS*LL];          // w^T @ shared accumulator
__device__ float g_wsum[BB*SS];             // w column sums
__device__ float g_st[BB*SS*CC];            // slice tokens after LatentTransition

// ---------------- helpers ---------------------------------------------------
__device__ __forceinline__ float warp_sum(float v){
#pragma unroll
    for (int o = 16; o > 0; o >>= 1) v += __shfl_xor_sync(0xffffffffu, v, o);
    return v;
}
__device__ __forceinline__ float gelu_exact(float x){
    return 0.5f * x * (1.0f + erff(x * 0.7071067811865476f));
}
__device__ __forceinline__ float sigmoid_(float x){
    return 1.0f / (1.0f + expf(-x));
}
__device__ __forceinline__ unsigned f2tf(float x){
    unsigned u; asm("cvt.rna.tf32.f32 %0, %1;" : "=r"(u) : "f"(x)); return u;
}
__device__ __forceinline__ float tfbits(float x){   // tf32-rounded value as float bits
    return __uint_as_float(f2tf(x));
}
// D += A(16x8) * B(8x8), tf32 inputs, f32 accumulate
__device__ __forceinline__ void mma_tf32(float c[4], const unsigned a[4], const unsigned b[2]){
    asm volatile(
        "mma.sync.aligned.m16n8k8.row.col.f32.tf32.tf32.f32 "
        "{%0,%1,%2,%3}, {%4,%5,%6,%7}, {%8,%9}, {%0,%1,%2,%3};\n"
        : "+f"(c[0]), "+f"(c[1]), "+f"(c[2]), "+f"(c[3])
        : "r"(a[0]), "r"(a[1]), "r"(a[2]), "r"(a[3]), "r"(b[0]), "r"(b[1]));
}

// ---------------- zero the accumulators (graph-replay safe) -----------------
__global__ void hf_zero(){
    int i = blockIdx.x * 256 + threadIdx.x;
    if (i < BB*SS*LL) g_tacc[i] = 0.0f;
    if (i < BB*SS)    g_wsum[i] = 0.0f;
}

// =====================================================================
// K2: 256-token tile: LN1 -> shared = h@W1+b1 -> logits -> softmax w
//     -> write w, tacc += w^T @ shared, wsum += colsum(w).  tf32 MMA.
// 256 threads = 8 warps. GEMM1/2: warp = 32 rows x 64 cols.
// =====================================================================
__global__ void __launch_bounds__(256,1)
hf_k2(const float* __restrict__ x, const float* __restrict__ geom,
      const float* __restrict__ ln1g, const float* __restrict__ ln1b,
      const float* __restrict__ W1, const float* __restrict__ b1,
      const float* __restrict__ W3, const float* __restrict__ b3)
{
    extern __shared__ float sm[];
    float* sW     = sm;               // [256][72]  W1 / W3 (tf32 bits)
    float* sH     = sW + 256*72;      // [256][68]  h-chunk / geom / logits+w
    float* sS     = sH + 256*68;      // [256][72]  shared tile (tf32 bits)
    float* sStats = sS + 256*72;      // 512

    int tid = threadIdx.x, wid = tid >> 5, lane = tid & 31;
    int lr = lane >> 2, lk = lane & 3;
    int base  = blockIdx.x * 256;
    int batch = base >> 16;

    // ---- LN1 stats (warp per token) ----
    for (int r = 0; r < 32; r++){
        int t = wid*32 + r;
        const float* xp = x + (size_t)(base + t)*CC;
        float s1 = 0.f, s2 = 0.f;
#pragma unroll
        for (int j = 0; j < 8; j++){ float v = xp[lane + 32*j]; s1 += v; s2 += v*v; }
        s1 = warp_sum(s1); s2 = warp_sum(s2);
        if (lane == 0){
            float m = s1 * (1.0f/CC);
            float var = s2 * (1.0f/CC) - m*m;
            sStats[2*t]   = m;
            sStats[2*t+1] = rsqrtf(var + 1e-5f);
        }
    }
    // W1 -> sW (tf32)
    for (int i = tid; i < 256*64; i += 256){
        int k = i >> 6, n = i & 63;
        sW[k*72 + n] = tfbits(W1[i]);
    }

    int r0 = wid * 32;
    float C[2][8][4];
#pragma unroll
    for (int rt = 0; rt < 2; rt++)
#pragma unroll
        for (int tc = 0; tc < 8; tc++)
#pragma unroll
            for (int q = 0; q < 4; q++) C[rt][tc][q] = 0.0f;

    // ---- GEMM1: shared = LN1(x) @ W1, K=256 in 4 chunks ----
    for (int kc = 0; kc < 4; kc++){
        __syncthreads();
        for (int i = tid; i < 256*64; i += 256){
            int t = i >> 6, c = i & 63;
            int kg = kc*64 + c;
            float v = x[(size_t)(base + t)*CC + kg];
            sH[t*68 + c] = tfbits((v - sStats[2*t]) * sStats[2*t+1] * ln1g[kg] + ln1b[kg]);
        }
        __syncthreads();
#pragma unroll
        for (int ks = 0; ks < 8; ks++){
            int k0 = ks*8;
            unsigned a[2][4];
#pragma unroll
            for (int rt = 0; rt < 2; rt++){
                int rr = r0 + rt*16 + lr;
                a[rt][0] = __float_as_uint(sH[rr*68     + k0 + lk]);
                a[rt][1] = __float_as_uint(sH[(rr+8)*68 + k0 + lk]);
                a[rt][2] = __float_as_uint(sH[rr*68     + k0 + lk + 4]);
                a[rt][3] = __float_as_uint(sH[(rr+8)*68 + k0 + lk + 4]);
            }
            int kg0 = kc*64 + k0;
#pragma unroll
            for (int tc = 0; tc < 8; tc++){
                unsigned b[2];
                b[0] = __float_as_uint(sW[(kg0 + lk)*72     + tc*8 + lr]);
                b[1] = __float_as_uint(sW[(kg0 + lk + 4)*72 + tc*8 + lr]);
                mma_tf32(C[0][tc], a[0], b);
                mma_tf32(C[1][tc], a[1], b);
            }
        }
    }
    __syncthreads();   // all warps done reading sH/sW before repurposing

    // write shared tile (tf32 bits, bias included)
#pragma unroll
    for (int rt = 0; rt < 2; rt++)
#pragma unroll
        for (int tc = 0; tc < 8; tc++){
            int rr = r0 + rt*16 + lr, cc = tc*8 + 2*lk;
            sS[rr*72 + cc]       = tfbits(C[rt][tc][0] + b1[cc]);
            sS[rr*72 + cc + 1]   = tfbits(C[rt][tc][1] + b1[cc+1]);
            sS[(rr+8)*72 + cc]   = tfbits(C[rt][tc][2] + b1[cc]);
            sS[(rr+8)*72 + cc+1] = tfbits(C[rt][tc][3] + b1[cc+1]);
        }

    // stage geom + W3, zero C
    for (int i = tid; i < 256*64; i += 256){
        int t = i >> 6, c = i & 63;
        sH[t*68 + c] = tfbits(geom[(size_t)(base + t)*64 + c]);
    }
    for (int i = tid; i < 128*64; i += 256){
        int k = i >> 6, n = i & 63;
        sW[k*72 + n] = tfbits(W3[i]);
    }
#pragma unroll
    for (int rt = 0; rt < 2; rt++)
#pragma unroll
        for (int tc = 0; tc < 8; tc++)
#pragma unroll
            for (int q = 0; q < 4; q++) C[rt][tc][q] = 0.0f;
    __syncthreads();

    // ---- GEMM2: logits = shared@W3[:64] + geom@W3[64:] ----
#pragma unroll
    for (int ks = 0; ks < 8; ks++){
        int k0 = ks*8;
        unsigned a[2][4];
#pragma unroll
        for (int rt = 0; rt < 2; rt++){
            int rr = r0 + rt*16 + lr;
            a[rt][0] = __float_as_uint(sS[rr*72     + k0 + lk]);
            a[rt][1] = __float_as_uint(sS[(rr+8)*72 + k0 + lk]);
            a[rt][2] = __float_as_uint(sS[rr*72     + k0 + lk + 4]);
            a[rt][3] = __float_as_uint(sS[(rr+8)*72 + k0 + lk + 4]);
        }
#pragma unroll
        for (int tc = 0; tc < 8; tc++){
            unsigned b[2];
            b[0] = __float_as_uint(sW[(k0 + lk)*72     + tc*8 + lr]);
            b[1] = __float_as_uint(sW[(k0 + lk + 4)*72 + tc*8 + lr]);
            mma_tf32(C[0][tc], a[0], b);
            mma_tf32(C[1][tc], a[1], b);
        }
    }
#pragma unroll
    for (int ks = 0; ks < 8; ks++){
        int k0 = ks*8;
        unsigned a[2][4];
#pragma unroll
        for (int rt = 0; rt < 2; rt++){
            int rr = r0 + rt*16 + lr;
            a[rt][0] = __float_as_uint(sH[rr*68     + k0 + lk]);
            a[rt][1] = __float_as_uint(sH[(rr+8)*68 + k0 + lk]);
            a[rt][2] = __float_as_uint(sH[rr*68     + k0 + lk + 4]);
            a[rt][3] = __float_as_uint(sH[(rr+8)*68 + k0 + lk + 4]);
        }
#pragma unroll
        for (int tc = 0; tc < 8; tc++){
            unsigned b[2];
            b[0] = __float_as_uint(sW[(64 + k0 + lk)*72     + tc*8 + lr]);
            b[1] = __float_as_uint(sW[(64 + k0 + lk + 4)*72 + tc*8 + lr]);
            mma_tf32(C[0][tc], a[0], b);
            mma_tf32(C[1][tc], a[1], b);
        }
    }
    __syncthreads();   // geom reads done -> overwrite sH with logits (fp32)
#pragma unroll
    for (int rt = 0; rt < 2; rt++)
#pragma unroll
        for (int tc = 0; tc < 8; tc++){
            int rr = r0 + rt*16 + lr, cc = tc*8 + 2*lk;
            sH[rr*68 + cc]       = C[rt][tc][0] + b3[cc];
            sH[rr*68 + cc + 1]   = C[rt][tc][1] + b3[cc+1];
            sH[(rr+8)*68 + cc]   = C[rt][tc][2] + b3[cc];
            sH[(rr+8)*68 + cc+1] = C[rt][tc][3] + b3[cc+1];
        }
    __syncthreads();

    // ---- softmax per token (thread = token) ----
    {
        float* row = sH + tid*68;
        float m = row[0];
#pragma unroll 8
        for (int c = 1; c < 64; c++) m = fmaxf(m, row[c]);
        float s = 0.f;
#pragma unroll 8
        for (int c = 0; c < 64; c++){ float e = expf(row[c] - m); row[c] = e; s += e; }
        float inv = 1.0f / s;
#pragma unroll 8
        for (int c = 0; c < 64; c++) row[c] *= inv;
    }
    __syncthreads();

    // ---- write w (coalesced), wsum ----
    for (int i = tid; i < 256*64; i += 256){
        int t = i >> 6, c = i & 63;
        g_w[(size_t)(base + t)*64 + c] = sH[t*68 + c];
    }
    if (tid < 64){
        float s = 0.f;
        for (int t = 0; t < 256; t++) s += sH[t*68 + tid];
        atomicAdd(&g_wsum[batch*64 + tid], s);
    }

    // ---- tacc += w^T @ shared: M=64(s) x N=64(l), K=256 tokens ----
    {
        int wm = wid & 3, wn = wid >> 2;
        int s0 = wm*16, n0b = wn*32;
        float C2[4][4];
#pragma unroll
        for (int tc = 0; tc < 4; tc++)
#pragma unroll
            for (int q = 0; q < 4; q++) C2[tc][q] = 0.0f;
        for (int ks = 0; ks < 32; ks++){
            int k0 = ks*8;
            unsigned a[4];
            a[0] = f2tf(sH[(k0 + lk)*68     + s0 + lr]);
            a[1] = f2tf(sH[(k0 + lk)*68     + s0 + lr + 8]);
            a[2] = f2tf(sH[(k0 + lk + 4)*68 + s0 + lr]);
            a[3] = f2tf(sH[(k0 + lk + 4)*68 + s0 + lr + 8]);
#pragma unroll
            for (int tc = 0; tc < 4; tc++){
                unsigned b[2];
                b[0] = __float_as_uint(sS[(k0 + lk)*72     + n0b + tc*8 + lr]);
                b[1] = __float_as_uint(sS[(k0 + lk + 4)*72 + n0b + tc*8 + lr]);
                mma_tf32(C2[tc], a, b);
            }
        }
        float* dst = g_tacc + batch*4096;
#pragma unroll
        for (int tc = 0; tc < 4; tc++){
            int cc = n0b + tc*8 + 2*lk;
            atomicAdd(&dst[(s0 + lr)*64 + cc],       C2[tc][0]);
            atomicAdd(&dst[(s0 + lr)*64 + cc + 1],   C2[tc][1]);
            atomicAdd(&dst[(s0 + lr + 8)*64 + cc],   C2[tc][2]);
            atomicAdd(&dst[(s0 + lr + 8)*64 + cc+1], C2[tc][3]);
        }
    }
}

// =====================================================================
// B: slice head (tacc@W2 -> slice) + LatentTransition (per batch, fp32)
// =====================================================================
__global__ void hf_b(const float* __restrict__ W2,  const float* __restrict__ b2,
                     const float* __restrict__ dW,  const float* __restrict__ db,
                     const float* __restrict__ dng, const float* __restrict__ dnb,
                     const float* __restrict__ aW,  const float* __restrict__ ab,
                     const float* __restrict__ selfW, const float* __restrict__ ctxW,
                     const float* __restrict__ ong, const float* __restrict__ onb,
                     const float* __restrict__ uW,  const float* __restrict__ ub)
{
    extern __shared__ float sm[];
    float* sl     = sm;                  // 64*256 slice tokens
    float* ta     = sl + SS*CC;          // 64*64  tacc
    float* ws     = ta + SS*LL;          // 64
    float* wsinv  = ws + SS;             // 64
    float* dsm    = wsinv + SS;          // 64*64
    float* lsm    = dsm + SS*LL;         // 64*64
    float* awm    = lsm + SS*LL;         // 64*16
    float* awsinv = awm + SS*AA;         // 16
    float* anch   = awsinv + AA;         // 16*64
    float* ctxm   = anch + AA*LL;        // 64*64
    float* ulm    = ctxm + SS*LL;        // 64*64

    int tid = threadIdx.x, b = blockIdx.x;
    for (int i = tid; i < SS*LL; i += 256) ta[i] = g_tacc[b*SS*LL + i];
    if (tid < SS){
        float wv = g_wsum[b*SS + tid];
        ws[tid] = wv;
        wsinv[tid] = 1.0f / fmaxf(wv, 1e-6f);
    }
    __syncthreads();

    for (int i = tid; i < SS*CC; i += 256){
        int s = i >> 8, c = i & 255;
        float accv = 0.f;
        const float* tr = ta + s*LL;
        for (int l = 0; l < LL; l++) accv = fmaf(tr[l], W2[l*CC + c], accv);
        sl[i] = (accv + ws[s]*b2[c]) * wsinv[s];
    }
    __syncthreads();

    for (int i = tid; i < SS*LL; i += 256){
        int s = i >> 6, l = i & 63;
        float accv = db[l];
        const float* row = sl + s*CC;
        for (int c = 0; c < CC; c++) accv = fmaf(row[c], dW[c*LL + l], accv);
        dsm[i] = accv;
    }
    __syncthreads();

    if (tid < SS){
        int s = tid;
        float m = 0.f;
        for (int l = 0; l < LL; l++) m += dsm[s*LL + l];
        m *= (1.0f/LL);
        float v = 0.f;
        for (int l = 0; l < LL; l++){ float d = dsm[s*LL + l] - m; v += d*d; }
        v *= (1.0f/LL);
        float r = rsqrtf(v + 1e-5f);
        for (int l = 0; l < LL; l++)
            lsm[s*LL + l] = (dsm[s*LL + l] - m)*r*dng[l] + dnb[l];
    }
    __syncthreads();

    if (tid < SS){
        int s = tid;
        float lg[AA];
        for (int a = 0; a < AA; a++) lg[a] = ab[a];
        for (int l = 0; l < LL; l++){
            float v = lsm[s*LL + l];
            for (int a = 0; a < AA; a++) lg[a] = fmaf(v, aW[l*AA + a], lg[a]);
        }
        float m = lg[0];
        for (int a = 1; a < AA; a++) m = fmaxf(m, lg[a]);
        float ssum = 0.f;
        for (int a = 0; a < AA; a++){ lg[a] = expf(lg[a] - m); ssum += lg[a]; }
        float inv = 1.0f / ssum;
        for (int a = 0; a < AA; a++) awm[s*AA + a] = lg[a]*inv;
    }
    __syncthreads();

    if (tid < AA){
        float ssum = 0.f;
        for (int s = 0; s < SS; s++) ssum += awm[s*AA + tid];
        awsinv[tid] = 1.0f / fmaxf(ssum, 1e-6f);
    }
    __syncthreads();

    for (int i = tid; i < AA*LL; i += 256){
        int a = i >> 6, d = i & 63;
        float accv = 0.f;
        for (int s = 0; s < SS; s++) accv = fmaf(awm[s*AA + a], lsm[s*LL + d], accv);
        anch[i] = accv * awsinv[a];
    }
    __syncthreads();

    for (int i = tid; i < SS*LL; i += 256){
        int s = i >> 6, d = i & 63;
        float accv = 0.f;
        for (int a = 0; a < AA; a++) accv = fmaf(awm[s*AA + a], anch[a*LL + d], accv);
        ctxm[i] = accv;
    }
    __syncthreads();

    for (int i = tid; i < SS*LL; i += 256){
        int s = i >> 6, l = i & 63;
        float accv = 0.f;
        for (int d = 0; d < LL; d++) accv = fmaf(lsm[s*LL + d], selfW[d*LL + l], accv);
        for (int d = 0; d < LL; d++) accv = fmaf(ctxm[s*LL + d], ctxW[d*LL + l], accv);
        ulm[i] = lsm[i] + gelu_exact(accv);
    }
    __syncthreads();

    if (tid < SS){
        int s = tid;
        float m = 0.f;
        for (int l = 0; l < LL; l++) m += ulm[s*LL + l];
        m *= (1.0f/LL);
        float v = 0.f;
        for (int l = 0; l < LL; l++){ float d = ulm[s*LL + l] - m; v += d*d; }
        v *= (1.0f/LL);
        float r = rsqrtf(v + 1e-5f);
        for (int l = 0; l < LL; l++)
            ulm[s*LL + l] = (ulm[s*LL + l] - m)*r*ong[l] + onb[l];
    }
    __syncthreads();

    for (int i = tid; i < SS*CC; i += 256){
        int s = i >> 8, c = i & 255;
        float accv = ub[c];
        for (int l = 0; l < LL; l++) accv = fmaf(ulm[s*LL + l], uW[l*CC + c], accv);
        g_st[b*SS*CC + i] = accv;
    }
}

// =====================================================================
// K5: y = x + w@st (+ LN2 stats). M=128 tok, N=256, K=64. tf32 MMA.
// 512 threads = 16 warps in 4(M)x4(N); warp tile 32x64.
// =====================================================================
__global__ void __launch_bounds__(512,1)
hf_k5(const float* __restrict__ x)
{
    extern __shared__ float sm[];
    float* sSt = sm;             // [64][264] st (tf32 bits)
    float* sWt = sSt + 64*264;   // [128][68] w  (tf32 bits)
    float* sS1 = sWt + 128*68;   // 128
    float* sS2 = sS1 + 128;      // 128

    int tid = threadIdx.x, wid = tid >> 5, lane = tid & 31;
    int lr = lane >> 2, lk = lane & 3;
    int base  = blockIdx.x * 128;
    int batch = base >> 16;

    for (int i = tid; i < 64*256; i += 512){
        int k = i >> 8, n = i & 255;
        sSt[k*264 + n] = tfbits(g_st[batch*16384 + i]);
    }
    for (int i = tid; i < 128*64; i += 512){
        int t = i >> 6, c = i & 63;
        sWt[t*68 + c] = tfbits(g_w[(size_t)(base + t)*64 + c]);
    }
    if (tid < 128){ sS1[tid] = 0.f; sS2[tid] = 0.f; }
    __syncthreads();

    int wm = wid & 3, wn = wid >> 2;
    int r0 = wm*32, n0b = wn*64;
    float C[2][8][4];
#pragma unroll
    for (int rt = 0; rt < 2; rt++)
#pragma unroll
        for (int tc = 0; tc < 8; tc++)
#pragma unroll
            for (int q = 0; q < 4; q++) C[rt][tc][q] = 0.0f;

#pragma unroll
    for (int ks = 0; ks < 8; ks++){
        int k0 = ks*8;
        unsigned a[2][4];
#pragma unroll
        for (int rt = 0; rt < 2; rt++){
            int rr = r0 + rt*16 + lr;
            a[rt][0] = __float_as_uint(sWt[rr*68     + k0 + lk]);
            a[rt][1] = __float_as_uint(sWt[(rr+8)*68 + k0 + lk]);
            a[rt][2] = __float_as_uint(sWt[rr*68     + k0 + lk + 4]);
            a[rt][3] = __float_as_uint(sWt[(rr+8)*68 + k0 + lk + 4]);
        }
#pragma unroll
        for (int tc = 0; tc < 8; tc++){
            unsigned b[2];
            b[0] = __float_as_uint(sSt[(k0 + lk)*264     + n0b + tc*8 + lr]);
            b[1] = __float_as_uint(sSt[(k0 + lk + 4)*264 + n0b + tc*8 + lr]);
            mma_tf32(C[0][tc], a[0], b);
            mma_tf32(C[1][tc], a[1], b);
        }
    }

    // epilogue: y = C + x, write y, LN2 partial stats
#pragma unroll
    for (int rt = 0; rt < 2; rt++)
#pragma unroll
        for (int half = 0; half < 2; half++){
            int rloc = r0 + rt*16 + lr + half*8;
            float s1 = 0.f, s2 = 0.f;
#pragma unroll
            for (int tc = 0; tc < 8; tc++){
                int cc = n0b + tc*8 + 2*lk;
                size_t of = (size_t)(base + rloc)*256 + cc;
                float2 xv = *(const float2*)(x + of);
                float y0 = C[rt][tc][half*2]     + xv.x;
                float y1 = C[rt][tc][half*2 + 1] + xv.y;
                *(float2*)(g_y + of) = make_float2(y0, y1);
                s1 += y0 + y1;
                s2 += y0*y0 + y1*y1;
            }
            atomicAdd(&sS1[rloc], s1);
            atomicAdd(&sS2[rloc], s2);
        }
    __syncthreads();
    if (tid < 128){
        float m = sS1[tid] * (1.0f/256.0f);
        float var = sS2[tid] * (1.0f/256.0f) - m*m;
        g_stats[(size_t)(base + tid)*2]     = m;
        g_stats[(size_t)(base + tid)*2 + 1] = rsqrtf(var + 1e-5f);
    }
}

// =====================================================================
// K6: vg = LN2(y)@cm_in_W + b; act = gelu(v)*sigmoid(g). tf32 MMA.
// M=128, N=128, K=256. 256 threads = 8 warps in 4(M)x2(N).
// v tiles tc 0..3 (cols wn*32+tc*8), g tiles tc 4..7 (cols 64+wn*32+(tc-4)*8)
// =====================================================================
__global__ void __launch_bounds__(256,1)
hf_k6(const float* __restrict__ g2v, const float* __restrict__ b2v,
      const float* __restrict__ Win, const float* __restrict__ bin)
{
    extern __shared__ float sm[];
    float* sWin  = sm;             // [256][136] (tf32 bits)
    float* sH    = sWin + 256*136; // [128][68]  (tf32 bits)
    float* sStat = sH + 128*68;    // 256

    int tid = threadIdx.x, wid = tid >> 5, lane = tid & 31;
    int lr = lane >> 2, lk = lane & 3;
    int base = blockIdx.x * 128;

    for (int i = tid; i < 256*128; i += 256){
        int k = i >> 7, n = i & 127;
        sWin[k*136 + n] = tfbits(Win[i]);
    }
    if (tid < 128){
        sStat[2*tid]   = g_stats[(size_t)(base + tid)*2];
        sStat[2*tid+1] = g_stats[(size_t)(base + tid)*2 + 1];
    }

    int wm = wid & 3, wn = wid >> 2;
    int r0 = wm*32;
    float C[2][8][4];
#pragma unroll
    for (int rt = 0; rt < 2; rt++)
#pragma unroll
        for (int tc = 0; tc < 8; tc++)
#pragma unroll
            for (int q = 0; q < 4; q++) C[rt][tc][q] = 0.0f;

    for (int kc = 0; kc < 4; kc++){
        __syncthreads();
        for (int i = tid; i < 128*64; i += 256){
            int t = i >> 6, c = i & 63;
            int kg = kc*64 + c;
            float v = g_y[(size_t)(base + t)*256 + kg];
            sH[t*68 + c] = tfbits((v - sStat[2*t]) * sStat[2*t+1] * g2v[kg] + b2v[kg]);
        }
        __syncthreads();
#pragma unroll
        for (int ks = 0; ks < 8; ks++){
            int k0 = ks*8;
            unsigned a[2][4];
#pragma unroll
            for (int rt = 0; rt < 2; rt++){
                int rr = r0 + rt*16 + lr;
                a[rt][0] = __float_as_uint(sH[rr*68     + k0 + lk]);
                a[rt][1] = __float_as_uint(sH[(rr+8)*68 + k0 + lk]);
                a[rt][2] = __float_as_uint(sH[rr*68     + k0 + lk + 4]);
                a[rt][3] = __float_as_uint(sH[(rr+8)*68 + k0 + lk + 4]);
            }
            int kg0 = kc*64 + k0;
#pragma unroll
            for (int tc = 0; tc < 8; tc++){
                int n0 = (tc < 4) ? (wn*32 + tc*8) : (64 + wn*32 + (tc-4)*8);
                unsigned b[2];
                b[0] = __float_as_uint(sWin[(kg0 + lk)*136     + n0 + lr]);
                b[1] = __float_as_uint(sWin[(kg0 + lk + 4)*136 + n0 + lr]);
                mma_tf32(C[0][tc], a[0], b);
                mma_tf32(C[1][tc], a[1], b);
            }
        }
    }

    // GLU epilogue (v and g pairs live in the same thread)
#pragma unroll
    for (int rt = 0; rt < 2; rt++)
#pragma unroll
        for (int tc = 0; tc < 4; tc++){
            int cv = wn*32 + tc*8 + 2*lk;
            float bv0 = bin[cv], bv1 = bin[cv+1];
            float bg0 = bin[64 + cv], bg1 = bin[64 + cv + 1];
            int rr = r0 + rt*16 + lr;
            {
                float v0 = C[rt][tc][0] + bv0, v1 = C[rt][tc][1] + bv1;
                float gg0 = C[rt][tc+4][0] + bg0, gg1 = C[rt][tc+4][1] + bg1;
                *(float2*)(g_act + (size_t)(base + rr)*64 + cv) =
                    make_float2(gelu_exact(v0)*sigmoid_(gg0), gelu_exact(v1)*sigmoid_(gg1));
            }
            {
                float v0 = C[rt][tc][2] + bv0, v1 = C[rt][tc][3] + bv1;
                float gg0 = C[rt][tc+4][2] + bg0, gg1 = C[rt][tc+4][3] + bg1;
                *(float2*)(g_act + (size_t)(base + rr + 8)*64 + cv) =
                    make_float2(gelu_exact(v0)*sigmoid_(gg0), gelu_exact(v1)*sigmoid_(gg1));
            }
        }
}

// =====================================================================
// K7: out = y + act@cm_out_W + b. M=64 tok, N=256, K=64. tf32 MMA.
// 256 threads = 8 warps in 4(M)x2(N); warp tile 16x128.
// =====================================================================
__global__ void __launch_bounds__(256,1)
hf_k7(const float* __restrict__ Wout, const float* __restrict__ bout,
      float* __restrict__ out)
{
    extern __shared__ float sm[];
    float* sA = sm;           // [64][68]  act (tf32 bits)
    float* sW = sA + 64*68;   // [64][264] Wout (tf32 bits)

    int tid = threadIdx.x, wid = tid >> 5, lane = tid & 31;
    int lr = lane >> 2, lk = lane & 3;
    int base = blockIdx.x * 64;

    for (int i = tid; i < 64*64; i += 256){
        int t = i >> 6, c = i & 63;
        sA[t*68 + c] = tfbits(g_act[(size_t)(base + t)*64 + c]);
    }
    for (int i = tid; i < 64*256; i += 256){
        int k = i >> 8, n = i & 255;
        sW[k*264 + n] = tfbits(Wout[i]);
    }
    __syncthreads();

    int wm = wid & 3, wn = wid >> 2;
    int r0 = wm*16, n0b = wn*128;
    float C[16][4];
#pragma unroll
    for (int tc = 0; tc < 16; tc++)
#pragma unroll
        for (int q = 0; q < 4; q++) C[tc][q] = 0.0f;

#pragma unroll
    for (int ks = 0; ks < 8; ks++){
        int k0 = ks*8;
        unsigned a[4];
        a[0] = __float_as_uint(sA[(r0 + lr)*68     + k0 + lk]);
        a[1] = __float_as_uint(sA[(r0 + lr + 8)*68 + k0 + lk]);
        a[2] = __float_as_uint(sA[(r0 + lr)*68     + k0 + lk + 4]);
        a[3] = __float_as_uint(sA[(r0 + lr + 8)*68 + k0 + lk + 4]);
#pragma unroll
        for (int tc = 0; tc < 16; tc++){
            unsigned b[2];
            b[0] = __float_as_uint(sW[(k0 + lk)*264     + n0b + tc*8 + lr]);
            b[1] = __float_as_uint(sW[(k0 + lk + 4)*264 + n0b + tc*8 + lr]);
            mma_tf32(C[tc], a, b);
        }
    }

#pragma unroll
    for (int tc = 0; tc < 16; tc++){
        int cc = n0b + tc*8 + 2*lk;
        {
            size_t of = (size_t)(base + r0 + lr)*256 + cc;
            float2 yv = *(const float2*)(g_y + of);
            *(float2*)(out + of) = make_float2(yv.x + C[tc][0] + bout[cc],
                                               yv.y + C[tc][1] + bout[cc+1]);
        }
        {
            size_t of = (size_t)(base + r0 + lr + 8)*256 + cc;
            float2 yv = *(const float2*)(g_y + of);
            *(float2*)(out + of) = make_float2(yv.x + C[tc][2] + bout[cc],
                                               yv.y + C[tc][3] + bout[cc+1]);
        }
    }
}

// ---------------- launcher ---------------------------------------------------
extern "C" void kernel_launch(void* const* d_in, const int* in_sizes, int n_in,
                              void* d_out, int out_size)
{
    const float* x    = (const float*)d_in[0];
    const float* geom = (const float*)d_in[1];
    const float* ln1g = (const float*)d_in[2];
    const float* ln1b = (const float*)d_in[3];
    const float* swW  = (const float*)d_in[4];
    const float* swb  = (const float*)d_in[5];
    const float* sfW  = (const float*)d_in[6];
    const float* sfb  = (const float*)d_in[7];
    const float* saW  = (const float*)d_in[8];
    const float* sab  = (const float*)d_in[9];
    const float* ldW  = (const float*)d_in[10];
    const float* ldb  = (const float*)d_in[11];
    const float* dng  = (const float*)d_in[12];
    const float* dnb  = (const float*)d_in[13];
    const float* laW  = (const float*)d_in[14];
    const float* lab  = (const float*)d_in[15];
    const float* lsW  = (const float*)d_in[16];
    const float* lcW  = (const float*)d_in[17];
    const float* ong  = (const float*)d_in[18];
    const float* onb  = (const float*)d_in[19];
    const float* luW  = (const float*)d_in[20];
    const float* lub  = (const float*)d_in[21];
    const float* ln2g = (const float*)d_in[22];
    const float* ln2b = (const float*)d_in[23];
    const float* ciW  = (const float*)d_in[24];
    const float* cib  = (const float*)d_in[25];
    const float* coW  = (const float*)d_in[26];
    const float* cob  = (const float*)d_in[27];
    float* out = (float*)d_out;

    const size_t smK2 = (size_t)(256*72 + 256*68 + 256*72 + 512) * 4;   // 219,136 B
    const size_t smB  = (size_t)(SS*CC + SS*LL + SS + SS + SS*LL + SS*LL +
                                 SS*AA + AA + AA*LL + SS*LL + SS*LL) * 4;
    const size_t smK5 = (size_t)(64*264 + 128*68 + 256) * 4;            // 103,424 B
    const size_t smK6 = (size_t)(256*136 + 128*68 + 256) * 4;           // 175,104 B
    const size_t smK7 = (size_t)(64*68 + 64*264) * 4;                   //  84,992 B

    cudaFuncSetAttribute(hf_k2, cudaFuncAttributeMaxDynamicSharedMemorySize, (int)smK2);
    cudaFuncSetAttribute(hf_b,  cudaFuncAttributeMaxDynamicSharedMemorySize, (int)smB);
    cudaFuncSetAttribute(hf_k5, cudaFuncAttributeMaxDynamicSharedMemorySize, (int)smK5);
    cudaFuncSetAttribute(hf_k6, cudaFuncAttributeMaxDynamicSharedMemorySize, (int)smK6);
    cudaFuncSetAttribute(hf_k7, cudaFuncAttributeMaxDynamicSharedMemorySize, (int)smK7);

    hf_zero<<<(BB*SS*LL + 255)/256, 256>>>();
    hf_k2<<<BN/256, 256, smK2>>>(x, geom, ln1g, ln1b, swW, swb, saW, sab);
    hf_b <<<BB,     256, smB >>>(sfW, sfb, ldW, ldb, dng, dnb, laW, lab,
                                 lsW, lcW, ong, onb, luW, lub);
    hf_k5<<<BN/128, 512, smK5>>>(x);
    hf_k6<<<BN/128, 256, smK6>>>(ln2g, ln2b, ciW, cib);
    hf_k7<<<BN/64,  256, smK7>>>(coW, cob, out);
}